// round 6
// baseline (speedup 1.0000x reference)
#include <cuda_runtime.h>
#include <cuda_bf16.h>

#define NN 50000
#define NE 800000
#define NF 100

// Folded projection vectors + scratch accumulators (no allocation allowed).
__device__ __align__(16) float g_wl[2][100];   // node-left  fold
__device__ __align__(16) float g_wr[2][100];   // node-right fold
__device__ __align__(16) float g_we[2][200];   // edge fold (raw 0..99, time 100..199)
__device__ float g_bias[6];                    // bl0 bl1 br0 br1 be0 be1
__device__ float g_el[NN * 2];
__device__ float g_er[NN * 2];
__device__ float g_nsum[NN * 2];               // sum exp(e)       per (node, head)
__device__ float g_psum[NN * 2];               // sum exp(e)*el'   per (node, head)

__device__ __forceinline__ float warp_sum(float v) {
#pragma unroll
    for (int o = 16; o > 0; o >>= 1) v += __shfl_xor_sync(0xffffffffu, v, o);
    return v;
}

// ---------------------------------------------------------------------------
// K0: fold fc weights/biases through the attention vectors.
// One warp per output scalar: 806 warp-tasks.
//   task [0,200):   wl[h][k] = sum_f fcnw[k*200 + h*100 + f] * attn_l[h*100+f]
//   task [200,400): wr
//   task [400,800): we[h][j] = sum_f fcew[j*200 + h*100 + f] * attn_e[h*100+f]
//   task [800,806): bl0 bl1 br0 br1 be0 be1
// ---------------------------------------------------------------------------
__global__ void k_prep(const float* __restrict__ fcnw, const float* __restrict__ fcnb,
                       const float* __restrict__ fcew, const float* __restrict__ fceb,
                       const float* __restrict__ al, const float* __restrict__ ar,
                       const float* __restrict__ ae) {
    int w = (blockIdx.x * blockDim.x + threadIdx.x) >> 5;
    int lane = threadIdx.x & 31;
    if (w < 400) {
        const float* av = (w < 200) ? al : ar;
        int t = (w < 200) ? w : (w - 200);
        int h = t / 100, k = t % 100;
        float s = 0.f;
        for (int f = lane; f < 100; f += 32)
            s += fcnw[k * 200 + h * 100 + f] * av[h * 100 + f];
        s = warp_sum(s);
        if (lane == 0) { if (w < 200) g_wl[h][k] = s; else g_wr[h][k] = s; }
    } else if (w < 800) {
        int u = w - 400;
        int h = u / 200, j = u % 200;
        float s = 0.f;
        for (int f = lane; f < 100; f += 32)
            s += fcew[j * 200 + h * 100 + f] * ae[h * 100 + f];
        s = warp_sum(s);
        if (lane == 0) g_we[h][j] = s;
    } else if (w < 806) {
        int t = w - 800;
        int h = t & 1;
        const float* bv = (t < 4) ? fcnb : fceb;
        const float* av = (t < 2) ? al : ((t < 4) ? ar : ae);
        float s = 0.f;
        for (int f = lane; f < 100; f += 32)
            s += bv[h * 100 + f] * av[h * 100 + f];
        s = warp_sum(s);
        if (lane == 0) g_bias[t] = s;
    }
}

// ---------------------------------------------------------------------------
// K1: per-node el/er (warp per node, float4 row loads) + zero accumulators.
// ---------------------------------------------------------------------------
__global__ void k_node(const float* __restrict__ memory) {
    int n = (blockIdx.x * blockDim.x + threadIdx.x) >> 5;
    int lane = threadIdx.x & 31;
    if (n >= NN) return;
    float l0 = 0.f, l1 = 0.f, r0 = 0.f, r1 = 0.f;
    if (lane < 25) {                       // 25 lanes * float4 = 100 floats
        float4 v  = ((const float4*)(memory + (long long)n * NF))[lane];
        float4 a0 = ((const float4*)g_wl[0])[lane];
        float4 a1 = ((const float4*)g_wl[1])[lane];
        float4 b0 = ((const float4*)g_wr[0])[lane];
        float4 b1 = ((const float4*)g_wr[1])[lane];
        l0 = v.x * a0.x + v.y * a0.y + v.z * a0.z + v.w * a0.w;
        l1 = v.x * a1.x + v.y * a1.y + v.z * a1.z + v.w * a1.w;
        r0 = v.x * b0.x + v.y * b0.y + v.z * b0.z + v.w * b0.w;
        r1 = v.x * b1.x + v.y * b1.y + v.z * b1.z + v.w * b1.w;
    }
    l0 = warp_sum(l0); l1 = warp_sum(l1);
    r0 = warp_sum(r0); r1 = warp_sum(r1);
    if (lane == 0) {
        g_el[n * 2 + 0] = l0 + g_bias[0];
        g_el[n * 2 + 1] = l1 + g_bias[1];
        g_er[n * 2 + 0] = r0 + g_bias[2];
        g_er[n * 2 + 1] = r1 + g_bias[3];
        g_nsum[n * 2 + 0] = 0.f; g_nsum[n * 2 + 1] = 0.f;
        g_psum[n * 2 + 0] = 0.f; g_psum[n * 2 + 1] = 0.f;
    }
}

// ---------------------------------------------------------------------------
// K2: warp per edge. Fused: raw-feature dot, Fourier time encoding dot,
// attention logit, leaky-relu, exp, scatter-accumulate (no max pass — values
// bounded ~|e|<12, exp stays comfortably in fp32).
// ---------------------------------------------------------------------------
__global__ void k_edge(const float* __restrict__ eraw, const float* __restrict__ ets,
                       const float* __restrict__ nts,
                       const int* __restrict__ src, const int* __restrict__ dst,
                       const float* __restrict__ tw, const float* __restrict__ tb) {
    int e = (blockIdx.x * blockDim.x + threadIdx.x) >> 5;
    int lane = threadIdx.x & 31;
    if (e >= NE) return;
    int s = src[e];
    int d = dst[e];
    float h0 = 0.f, h1 = 0.f;
    if (lane < 25) {
        float dt = ets[e] - nts[s];
        // raw edge feature dot (one LDG.128 per lane covers the 400B row)
        float4 v = ((const float4*)(eraw + (long long)e * NF))[lane];
        float4 a = ((const float4*)g_we[0])[lane];
        float4 b = ((const float4*)g_we[1])[lane];
        h0 = v.x * a.x + v.y * a.y + v.z * a.z + v.w * a.w;
        h1 = v.x * b.x + v.y * b.y + v.z * b.z + v.w * b.w;
        // Fourier time encoding: te[t] = cos(dt*tw[t]+tb[t]), t = 4*lane..4*lane+3
        float4 wv = ((const float4*)tw)[lane];
        float4 bv = ((const float4*)tb)[lane];
        float c0 = __cosf(dt * wv.x + bv.x);
        float c1 = __cosf(dt * wv.y + bv.y);
        float c2 = __cosf(dt * wv.z + bv.z);
        float c3 = __cosf(dt * wv.w + bv.w);
        float4 ea = ((const float4*)(g_we[0] + 100))[lane];
        float4 eb = ((const float4*)(g_we[1] + 100))[lane];
        h0 += c0 * ea.x + c1 * ea.y + c2 * ea.z + c3 * ea.w;
        h1 += c0 * eb.x + c1 * eb.y + c2 * eb.z + c3 * eb.w;
    }
    h0 = warp_sum(h0);
    h1 = warp_sum(h1);
    if (lane < 2) {                        // lane = head index
        float ee  = (lane == 0 ? h0 : h1) + g_bias[4 + lane];
        float elp = g_el[s * 2 + lane] + ee;          // el' = el[src] + ee
        float ev  = elp + g_er[d * 2 + lane];         // e  = el' + er[dst]
        ev = ev > 0.f ? ev : 0.2f * ev;               // leaky_relu
        float ex = __expf(ev);
        atomicAdd(&g_nsum[d * 2 + lane], ex);
        atomicAdd(&g_psum[d * 2 + lane], ex * elp);
    }
}

// ---------------------------------------------------------------------------
// K3: out[n,f] = memory[n,f] + 0.5*(ft0 + ft1),  ft_h = psum/nsum (0 if empty)
// ---------------------------------------------------------------------------
__global__ void k_out(const float* __restrict__ memory, float* __restrict__ out) {
    int i = blockIdx.x * blockDim.x + threadIdx.x;
    if (i >= NN * NF) return;
    int n = i / NF;
    float s0 = g_nsum[n * 2 + 0], s1 = g_nsum[n * 2 + 1];
    float f0 = s0 > 0.f ? __fdividef(g_psum[n * 2 + 0], s0) : 0.f;
    float f1 = s1 > 0.f ? __fdividef(g_psum[n * 2 + 1], s1) : 0.f;
    out[i] = memory[i] + 0.5f * (f0 + f1);
}

extern "C" void kernel_launch(void* const* d_in, const int* in_sizes, int n_in,
                              void* d_out, int out_size) {
    const float* memory = (const float*)d_in[0];
    const float* node_ts = (const float*)d_in[1];
    const float* eraw   = (const float*)d_in[2];
    const float* ets    = (const float*)d_in[3];
    const float* tw     = (const float*)d_in[4];
    const float* tb     = (const float*)d_in[5];
    const float* fcnw   = (const float*)d_in[6];
    const float* fcnb   = (const float*)d_in[7];
    const float* fcew   = (const float*)d_in[8];
    const float* fceb   = (const float*)d_in[9];
    const float* al     = (const float*)d_in[10];
    const float* ar     = (const float*)d_in[11];
    const float* ae     = (const float*)d_in[12];
    const int*   src    = (const int*)d_in[13];
    const int*   dst    = (const int*)d_in[14];
    float* out = (float*)d_out;

    // K0: 806 warp-tasks
    k_prep<<<(806 * 32 + 255) / 256, 256>>>(fcnw, fcnb, fcew, fceb, al, ar, ae);
    // K1: warp per node
    k_node<<<(NN * 32 + 255) / 256, 256>>>(memory);
    // K2: warp per edge
    k_edge<<<(NE * 32 + 255) / 256, 256>>>(eraw, ets, node_ts, src, dst, tw, tb);
    // K3: element-wise output
    k_out<<<(NN * NF + 255) / 256, 256>>>(memory, out);
}

// round 8
// speedup vs baseline: 1.6311x; 1.6311x over previous
#include <cuda_runtime.h>
#include <cuda_bf16.h>

#define NN 50000
#define NE 800000
#define NF 100
#define TILE 64            // edges per block in k_edge
#define PADV 27            // float4 per padded smem row (108 floats -> conflict-free)

// Folded projection vectors + scratch (no allocation allowed).
__device__ __align__(16) float g_wl[2][100];
__device__ __align__(16) float g_wr[2][100];
__device__ __align__(16) float g_we[2][200];   // [head][raw 0..99 | time 100..199]
__device__ float  g_bias[6];                   // bl0 bl1 br0 br1 be0 be1
__device__ __align__(8)  float2 g_el2[NN];     // (el_h0, el_h1)
__device__ __align__(8)  float2 g_er2[NN];
__device__ __align__(16) float4 g_acc[NN];     // {nsum0, psum0, nsum1, psum1}

__device__ __forceinline__ float warp_sum(float v) {
#pragma unroll
    for (int o = 16; o > 0; o >>= 1) v += __shfl_xor_sync(0xffffffffu, v, o);
    return v;
}

// ---------------------------------------------------------------------------
// K0: fold fc weights/biases through attention vectors (806 warp-tasks).
// ---------------------------------------------------------------------------
__global__ void k_prep(const float* __restrict__ fcnw, const float* __restrict__ fcnb,
                       const float* __restrict__ fcew, const float* __restrict__ fceb,
                       const float* __restrict__ al, const float* __restrict__ ar,
                       const float* __restrict__ ae) {
    int w = (blockIdx.x * blockDim.x + threadIdx.x) >> 5;
    int lane = threadIdx.x & 31;
    if (w < 400) {
        const float* av = (w < 200) ? al : ar;
        int t = (w < 200) ? w : (w - 200);
        int h = t / 100, k = t % 100;
        float s = 0.f;
        for (int f = lane; f < 100; f += 32)
            s += fcnw[k * 200 + h * 100 + f] * av[h * 100 + f];
        s = warp_sum(s);
        if (lane == 0) { if (w < 200) g_wl[h][k] = s; else g_wr[h][k] = s; }
    } else if (w < 800) {
        int u = w - 400;
        int h = u / 200, j = u % 200;
        float s = 0.f;
        for (int f = lane; f < 100; f += 32)
            s += fcew[j * 200 + h * 100 + f] * ae[h * 100 + f];
        s = warp_sum(s);
        if (lane == 0) g_we[h][j] = s;
    } else if (w < 806) {
        int t = w - 800;
        int h = t & 1;
        const float* bv = (t < 4) ? fcnb : fceb;
        const float* av = (t < 2) ? al : ((t < 4) ? ar : ae);
        float s = 0.f;
        for (int f = lane; f < 100; f += 32)
            s += bv[h * 100 + f] * av[h * 100 + f];
        s = warp_sum(s);
        if (lane == 0) g_bias[t] = s;
    }
}

// ---------------------------------------------------------------------------
// K1: per-node el/er (warp per node) + zero accumulators.
// ---------------------------------------------------------------------------
__global__ void k_node(const float* __restrict__ memory) {
    int n = (blockIdx.x * blockDim.x + threadIdx.x) >> 5;
    int lane = threadIdx.x & 31;
    if (n >= NN) return;
    float l0 = 0.f, l1 = 0.f, r0 = 0.f, r1 = 0.f;
    if (lane < 25) {
        float4 v  = ((const float4*)(memory + (long long)n * NF))[lane];
        float4 a0 = ((const float4*)g_wl[0])[lane];
        float4 a1 = ((const float4*)g_wl[1])[lane];
        float4 b0 = ((const float4*)g_wr[0])[lane];
        float4 b1 = ((const float4*)g_wr[1])[lane];
        l0 = v.x * a0.x + v.y * a0.y + v.z * a0.z + v.w * a0.w;
        l1 = v.x * a1.x + v.y * a1.y + v.z * a1.z + v.w * a1.w;
        r0 = v.x * b0.x + v.y * b0.y + v.z * b0.z + v.w * b0.w;
        r1 = v.x * b1.x + v.y * b1.y + v.z * b1.z + v.w * b1.w;
    }
    l0 = warp_sum(l0); l1 = warp_sum(l1);
    r0 = warp_sum(r0); r1 = warp_sum(r1);
    if (lane == 0) {
        g_el2[n] = make_float2(l0 + g_bias[0], l1 + g_bias[1]);
        g_er2[n] = make_float2(r0 + g_bias[2], r1 + g_bias[3]);
        g_acc[n] = make_float4(0.f, 0.f, 0.f, 0.f);
    }
}

// ---------------------------------------------------------------------------
// K2: tiled thread-per-edge. Stage 64 edge rows into padded smem (coalesced),
// copy fold vectors into smem once per block, then each thread computes its
// edge's full 200-dim attention dot (raw + fused Fourier time encoding) with
// conflict-free LDS and full-lane FFMA. Exp-softmax accumulation via RED.
// ---------------------------------------------------------------------------
__global__ void __launch_bounds__(TILE, 7)
k_edge(const float* __restrict__ eraw, const float* __restrict__ ets,
       const float* __restrict__ nts,
       const int* __restrict__ src, const int* __restrict__ dst,
       const float* __restrict__ tw, const float* __restrict__ tb) {
    __shared__ __align__(16) float4 s_tile[TILE * PADV];   // 64*27*16 = 27648 B
    __shared__ __align__(16) float4 s_c[6][25];            // w0r w1r w0t w1t tw tb

    const int t = threadIdx.x;

    if (t < 25) {
        s_c[0][t] = ((const float4*)g_we[0])[t];
        s_c[1][t] = ((const float4*)g_we[1])[t];
        s_c[2][t] = ((const float4*)(g_we[0] + 100))[t];
        s_c[3][t] = ((const float4*)(g_we[1] + 100))[t];
        s_c[4][t] = ((const float4*)tw)[t];
        s_c[5][t] = ((const float4*)tb)[t];
    }

    // stage: 64 rows x 25 float4 = 1600 float4, coalesced, 25 per thread
    const float4* gsrc = (const float4*)eraw + (size_t)blockIdx.x * (TILE * 25);
#pragma unroll
    for (int k = 0; k < 25; k++) {
        unsigned g = t + k * TILE;
        unsigned row = g / 25u, col = g % 25u;     // const-div -> mul/shift
        s_tile[row * PADV + col] = gsrc[g];
    }
    __syncthreads();

    const int e = blockIdx.x * TILE + t;
    const int s = src[e];
    const int d = dst[e];
    const float dt = ets[e] - nts[s];

    const float4* myrow = &s_tile[t * PADV];
    float h0 = 0.f, h1 = 0.f;
#pragma unroll
    for (int j = 0; j < 25; j++) {                 // raw-feature dot
        float4 v = myrow[j];
        float4 a = s_c[0][j], b = s_c[1][j];
        h0 = fmaf(v.x, a.x, fmaf(v.y, a.y, fmaf(v.z, a.z, fmaf(v.w, a.w, h0))));
        h1 = fmaf(v.x, b.x, fmaf(v.y, b.y, fmaf(v.z, b.z, fmaf(v.w, b.w, h1))));
    }
#pragma unroll
    for (int j = 0; j < 25; j++) {                 // Fourier time-encoding dot
        float4 wv = s_c[4][j], bv = s_c[5][j];
        float c0 = __cosf(fmaf(dt, wv.x, bv.x));
        float c1 = __cosf(fmaf(dt, wv.y, bv.y));
        float c2 = __cosf(fmaf(dt, wv.z, bv.z));
        float c3 = __cosf(fmaf(dt, wv.w, bv.w));
        float4 a = s_c[2][j], b = s_c[3][j];
        h0 = fmaf(c0, a.x, fmaf(c1, a.y, fmaf(c2, a.z, fmaf(c3, a.w, h0))));
        h1 = fmaf(c0, b.x, fmaf(c1, b.y, fmaf(c2, b.z, fmaf(c3, b.w, h1))));
    }

    const float2 elv = g_el2[s];
    const float2 erv = g_er2[d];
    float* acc = (float*)&g_acc[d];

    // head 0
    {
        float ee  = h0 + g_bias[4];
        float elp = elv.x + ee;
        float ev  = elp + erv.x;
        ev = ev > 0.f ? ev : 0.2f * ev;
        float ex = __expf(ev);
        atomicAdd(acc + 0, ex);
        atomicAdd(acc + 1, ex * elp);
    }
    // head 1
    {
        float ee  = h1 + g_bias[5];
        float elp = elv.y + ee;
        float ev  = elp + erv.y;
        ev = ev > 0.f ? ev : 0.2f * ev;
        float ex = __expf(ev);
        atomicAdd(acc + 2, ex);
        atomicAdd(acc + 3, ex * elp);
    }
}

// ---------------------------------------------------------------------------
// K3: out = memory + 0.5*(ft0+ft1), float4-vectorized (25 float4 per node,
// vectors never straddle a node boundary).
// ---------------------------------------------------------------------------
__global__ void k_out(const float* __restrict__ memory, float* __restrict__ out) {
    int i4 = blockIdx.x * blockDim.x + threadIdx.x;
    if (i4 >= NN * 25) return;
    unsigned n = (unsigned)i4 / 25u;
    float4 acc = g_acc[n];
    float f0 = acc.x > 0.f ? __fdividef(acc.y, acc.x) : 0.f;
    float f1 = acc.z > 0.f ? __fdividef(acc.w, acc.z) : 0.f;
    float add = 0.5f * (f0 + f1);
    float4 m = ((const float4*)memory)[i4];
    float4 o = make_float4(m.x + add, m.y + add, m.z + add, m.w + add);
    ((float4*)out)[i4] = o;
}

extern "C" void kernel_launch(void* const* d_in, const int* in_sizes, int n_in,
                              void* d_out, int out_size) {
    const float* memory = (const float*)d_in[0];
    const float* node_ts = (const float*)d_in[1];
    const float* eraw   = (const float*)d_in[2];
    const float* ets    = (const float*)d_in[3];
    const float* tw     = (const float*)d_in[4];
    const float* tb     = (const float*)d_in[5];
    const float* fcnw   = (const float*)d_in[6];
    const float* fcnb   = (const float*)d_in[7];
    const float* fcew   = (const float*)d_in[8];
    const float* fceb   = (const float*)d_in[9];
    const float* al     = (const float*)d_in[10];
    const float* ar     = (const float*)d_in[11];
    const float* ae     = (const float*)d_in[12];
    const int*   src    = (const int*)d_in[13];
    const int*   dst    = (const int*)d_in[14];
    float* out = (float*)d_out;

    k_prep<<<(806 * 32 + 255) / 256, 256>>>(fcnw, fcnb, fcew, fceb, al, ar, ae);
    k_node<<<(NN * 32 + 255) / 256, 256>>>(memory);
    k_edge<<<NE / TILE, TILE>>>(eraw, ets, node_ts, src, dst, tw, tb);
    k_out<<<(NN * 25 + 255) / 256, 256>>>(memory, out);
}